// round 4
// baseline (speedup 1.0000x reference)
#include <cuda_runtime.h>

#define BB 2048
#define TT 1024
#define DD 64
#define HH 16
#define CH 64              // t-chunk per warp in K1
#define NW 16              // warps per K1 block
#define INV_TAU (1.0f/6.0f)

typedef unsigned long long u64;

// xw scratch: [B, T, 16]
__device__ float g_xw[(size_t)BB * TT * HH];

__device__ __forceinline__ u64 pk2(float lo, float hi) {
    u64 r; asm("mov.b64 %0, {%1,%2};" : "=l"(r) : "f"(lo), "f"(hi)); return r;
}
__device__ __forceinline__ u64 mul2(u64 a, u64 b) {
    u64 r; asm("mul.rn.f32x2 %0, %1, %2;" : "=l"(r) : "l"(a), "l"(b)); return r;
}
__device__ __forceinline__ u64 fma2(u64 a, u64 b, u64 c) {
    u64 r; asm("fma.rn.f32x2 %0, %1, %2, %3;" : "=l"(r) : "l"(a), "l"(b), "l"(c)); return r;
}
__device__ __forceinline__ float hadd2(u64 a) {
    float lo, hi; asm("mov.b64 {%0,%1}, %2;" : "=f"(lo), "=f"(hi) : "l"(a)); return lo + hi;
}

// ============================================================================
// K1: syn affine chunk-scan + x_cat + input projection -> g_xw
// Block = 512 threads (16 warps) = one batch. Warp w owns t in [64w, 64w+64).
// Lane owns d-pair (2l, 2l+1) for syn; proj uses d-quad {self pair, (l^16) pair}
// and h-octet hi = l>>4 (30-instr butterfly over 16-lane halves).
// ============================================================================
__global__ void __launch_bounds__(512) k1_syn_proj(
    const float* __restrict__ inputs,   // [B,T,64]
    const float* __restrict__ syn_x0,   // [B,64]
    const float* __restrict__ w_ih,     // [128,16]
    float* __restrict__ out_xcat)       // [B,T,128]
{
    __shared__ float Asm[NW][DD];
    __shared__ float Bsm[NW][DD];
    __shared__ float Ssm[NW][DD];

    const int b    = blockIdx.x;
    const int tid  = threadIdx.x;
    const int w    = tid >> 5;
    const int lane = tid & 31;
    const int t0   = w * CH;

    // ---- register-stationary weights (quad layout) ----
    const int hi = lane >> 4;            // h-octet
    const int pp = lane ^ 16;            // partner lane (other d-pair of quad)
    u64 wSa[8], wPa[8], wSb[8], wPb[8];
#pragma unroll
    for (int hh = 0; hh < 8; hh++) {
        int h = hi * 8 + hh;
        wSa[hh] = pk2(w_ih[(2*lane   )*HH + h], w_ih[(2*lane+1 )*HH + h]);
        wPa[hh] = pk2(w_ih[(2*pp     )*HH + h], w_ih[(2*pp+1   )*HH + h]);
        wSb[hh] = pk2(w_ih[(64+2*lane)*HH + h], w_ih[(64+2*lane+1)*HH + h]);
        wPb[hh] = pk2(w_ih[(64+2*pp  )*HH + h], w_ih[(64+2*pp+1)*HH + h]);
    }
    // final h this lane's butterfly result represents
    const int hsel = hi*8 + ((lane & 1) << 2) | (lane & 2) | ((lane >> 2) & 1);

    const float2* ip = reinterpret_cast<const float2*>(inputs)
                       + ((size_t)b*TT + t0)*(DD/2) + lane;

    // ---- phase 1: compose chunk affine (A,B) per owned d ----
    {
        float2 A = make_float2(1.f, 1.f);
        float2 Bc = make_float2(0.f, 0.f);
        float2 buf[4];
#pragma unroll
        for (int k = 0; k < 4; k++) buf[k] = ip[k*(DD/2)];
        for (int t = 0; t < CH; t++) {
            float2 in = buf[t & 3];
            if (t + 4 < CH) buf[t & 3] = ip[(t + 4)*(DD/2)];
            float kx = fmaf(0.5f, in.x, INV_TAU);
            float ky = fmaf(0.5f, in.y, INV_TAU);
            float ex = __expf(-kx);
            float ey = __expf(-ky);
            float rx = __fdividef(INV_TAU, kx);
            float ry = __fdividef(INV_TAU, ky);
            float bx = fmaf(-rx, ex, rx);      // r(1-e)
            float by = fmaf(-ry, ey, ry);
            A.x *= ex;  A.y *= ey;
            Bc.x = fmaf(ex, Bc.x, bx);
            Bc.y = fmaf(ey, Bc.y, by);
        }
        *reinterpret_cast<float2*>(&Asm[w][2*lane]) = A;
        *reinterpret_cast<float2*>(&Bsm[w][2*lane]) = Bc;
    }
    __syncthreads();

    // ---- phase 2: exclusive block scan over 16 chunks, per d ----
    if (tid < DD) {
        float s = syn_x0[b*DD + tid];
#pragma unroll
        for (int c = 0; c < NW; c++) {
            Ssm[c][tid] = s;
            s = fmaf(Asm[c][tid], s, Bsm[c][tid]);
        }
    }
    __syncthreads();

    // ---- phase 3: re-stream inputs, emit x_cat + xw ----
    float2 s = *reinterpret_cast<float2*>(&Ssm[w][2*lane]);
    float2* xc = reinterpret_cast<float2*>(out_xcat)
                 + ((size_t)b*TT + t0)*DD + lane;
    float* xwp = g_xw + ((size_t)b*TT + t0)*HH;

    float2 buf[4];
#pragma unroll
    for (int k = 0; k < 4; k++) buf[k] = ip[k*(DD/2)];

    for (int t = 0; t < CH; t++) {
        float2 in = buf[t & 3];
        if (t + 4 < CH) buf[t & 3] = ip[(t + 4)*(DD/2)];

        float kx = fmaf(0.5f, in.x, INV_TAU);
        float ky = fmaf(0.5f, in.y, INV_TAU);
        float ex = __expf(-kx);
        float ey = __expf(-ky);
        float rx = __fdividef(INV_TAU, kx);
        float ry = __fdividef(INV_TAU, ky);

        float2 sx;                       // syn(pre) * input
        sx.x = s.x * in.x;
        sx.y = s.y * in.y;

        xc[t*DD]      = in;              // x_cat[:, :64]
        xc[t*DD + 32] = sx;              // x_cat[:, 64:]

        s.x = fmaf(ex, s.x - rx, rx);
        s.y = fmaf(ey, s.y - ry, ry);

        // ---- quad exchange with partner lane (l^16) ----
        float ipx = __shfl_xor_sync(0xffffffffu, in.x, 16);
        float ipy = __shfl_xor_sync(0xffffffffu, in.y, 16);
        float spx = __shfl_xor_sync(0xffffffffu, sx.x, 16);
        float spy = __shfl_xor_sync(0xffffffffu, sx.y, 16);
        u64 inS = pk2(in.x, in.y), inP = pk2(ipx, ipy);
        u64 sxS = pk2(sx.x, sx.y), sxP = pk2(spx, spy);

        // ---- projection partials for this lane's h-octet ----
        float p8[8];
#pragma unroll
        for (int hh = 0; hh < 8; hh++) {
            u64 a = mul2(inS, wSa[hh]);
            a = fma2(inP, wPa[hh], a);
            a = fma2(sxS, wSb[hh], a);
            a = fma2(sxP, wPb[hh], a);
            p8[hh] = hadd2(a);
        }

        // ---- butterfly over 16-lane half (masks 1,2,4), fold at 8 ----
        float p4[4];
        {
            bool lo = (lane & 1) == 0;
#pragma unroll
            for (int i = 0; i < 4; i++) {
                float send = lo ? p8[4+i] : p8[i];
                float recv = __shfl_xor_sync(0xffffffffu, send, 1);
                p4[i] = (lo ? p8[i] : p8[4+i]) + recv;
            }
        }
        float p2_[2];
        {
            bool lo = (lane & 2) == 0;
#pragma unroll
            for (int i = 0; i < 2; i++) {
                float send = lo ? p4[2+i] : p4[i];
                float recv = __shfl_xor_sync(0xffffffffu, send, 2);
                p2_[i] = (lo ? p4[i] : p4[2+i]) + recv;
            }
        }
        float p1;
        {
            bool lo = (lane & 4) == 0;
            float send = lo ? p2_[1] : p2_[0];
            float recv = __shfl_xor_sync(0xffffffffu, send, 4);
            p1 = (lo ? p2_[0] : p2_[1]) + recv;
        }
        float r = p1 + __shfl_xor_sync(0xffffffffu, p1, 8);

        if (!(lane & 8)) xwp[t*HH + hsel] = r;
    }
}

// ============================================================================
// K2: sequential ReLU RNN + hidden + linear output. One warp per batch.
// ============================================================================
__global__ void __launch_bounds__(32) k2_rnn(
    const float* __restrict__ h0,       // [B,16]
    const float* __restrict__ w_hh,     // [16,16]
    const float* __restrict__ bias,     // [16]
    const float* __restrict__ lin_w,    // [16]
    const float* __restrict__ lin_b,    // [1]
    float* __restrict__ out_output,     // [B,T]
    float* __restrict__ out_hidden)     // [B,T,16]
{
    const int lane = threadIdx.x;
    const int b    = blockIdx.x;
    const int j    = lane & 15;

    float whh[HH];
#pragma unroll
    for (int i = 0; i < HH; i++) whh[i] = w_hh[i*HH + j];
    const float biasj = bias[j];
    const float lwj   = lin_w[j];
    const float lb    = lin_b[0];

    float hj = h0[b*HH + j];

    const float* xp = g_xw + (size_t)b*TT*HH + j;   // lanes 16-31 mirror
    float*      hid = out_hidden + (size_t)b*TT*HH;
    float*       op = out_output + (size_t)b*TT;

    float buf[4];
#pragma unroll
    for (int p = 0; p < 4; p++) buf[p] = xp[p*HH];

    for (int t = 0; t < TT; t++) {
        float xwv = buf[t & 3];
        if (t + 4 < TT) buf[t & 3] = xp[(t + 4)*HH];

        float a0 = xwv + biasj, a1 = 0.f, a2 = 0.f, a3 = 0.f;
#pragma unroll
        for (int i = 0; i < HH; i += 4) {
            float h0_ = __shfl_sync(0xffffffffu, hj, i);
            float h1_ = __shfl_sync(0xffffffffu, hj, i+1);
            float h2_ = __shfl_sync(0xffffffffu, hj, i+2);
            float h3_ = __shfl_sync(0xffffffffu, hj, i+3);
            a0 = fmaf(h0_, whh[i],   a0);
            a1 = fmaf(h1_, whh[i+1], a1);
            a2 = fmaf(h2_, whh[i+2], a2);
            a3 = fmaf(h3_, whh[i+3], a3);
        }
        hj = fmaxf((a0 + a1) + (a2 + a3), 0.0f);

        if (lane < HH) hid[t*HH + j] = hj;

        float v = hj * lwj;
        v += __shfl_xor_sync(0xffffffffu, v, 8);
        v += __shfl_xor_sync(0xffffffffu, v, 4);
        v += __shfl_xor_sync(0xffffffffu, v, 2);
        v += __shfl_xor_sync(0xffffffffu, v, 1);
        if (lane == 0) op[t] = v + lb;
    }
}

extern "C" void kernel_launch(void* const* d_in, const int* in_sizes, int n_in,
                              void* d_out, int out_size) {
    const float* inputs = (const float*)d_in[0];   // [B,T,64]
    const float* syn_x0 = (const float*)d_in[1];   // [B,64]
    const float* h0     = (const float*)d_in[2];   // [B,16]
    const float* w_ih   = (const float*)d_in[3];   // [128,16]
    const float* w_hh   = (const float*)d_in[4];   // [16,16]
    const float* bias   = (const float*)d_in[5];   // [16]
    const float* lin_w  = (const float*)d_in[6];   // [16,1]
    const float* lin_b  = (const float*)d_in[7];   // [1]

    float* out = (float*)d_out;
    // tuple concat order: output [B,T,1], hidden [B,T,16], x_cat [B,T,128]
    float* out_output = out;
    float* out_hidden = out + (size_t)BB*TT;
    float* out_xcat   = out + (size_t)BB*TT + (size_t)BB*TT*HH;

    k1_syn_proj<<<BB, 512>>>(inputs, syn_x0, w_ih, out_xcat);
    k2_rnn<<<BB, 32>>>(h0, w_hh, bias, lin_w, lin_b, out_output, out_hidden);
}

// round 5
// speedup vs baseline: 1.0095x; 1.0095x over previous
#include <cuda_runtime.h>

#define BB 2048
#define TT 1024
#define DD 64
#define HH 16
#define NW 8               // warps per K1 block
#define CH 128             // timesteps per K1 warp
#define INV_TAU (1.0f/6.0f)

typedef unsigned long long u64;

// xw scratch: [B, T, 16]
__device__ float g_xw[(size_t)BB * TT * HH];

__device__ __forceinline__ u64 pk2(float lo, float hi) {
    u64 r; asm("mov.b64 %0, {%1,%2};" : "=l"(r) : "f"(lo), "f"(hi)); return r;
}
__device__ __forceinline__ u64 mul2(u64 a, u64 b) {
    u64 r; asm("mul.rn.f32x2 %0, %1, %2;" : "=l"(r) : "l"(a), "l"(b)); return r;
}
__device__ __forceinline__ u64 fma2(u64 a, u64 b, u64 c) {
    u64 r; asm("fma.rn.f32x2 %0, %1, %2, %3;" : "=l"(r) : "l"(a), "l"(b), "l"(c)); return r;
}
__device__ __forceinline__ float hadd2(u64 a) {
    float lo, hi; asm("mov.b64 {%0,%1}, %2;" : "=f"(lo), "=f"(hi) : "l"(a)); return lo + hi;
}

// exp(-k) for k in [1/6, 2/3): degree-5 poly about c=5/12. rel err ~4e-7.
// Replaces MUFU.EX2 (rt=8/SMSP) with 6 fma-pipe ops.
__device__ __forceinline__ float expnk(float k) {
    const float E = 0.6592406302004438f;         // exp(-5/12)
    float x = k - 0.4166666666666667f;
    float p = -E / 120.0f;
    p = fmaf(p, x,  E / 24.0f);
    p = fmaf(p, x, -E / 6.0f);
    p = fmaf(p, x,  E * 0.5f);
    p = fmaf(p, x, -E);
    p = fmaf(p, x,  E);
    return p;
}

// ============================================================================
// K1: synaptic chunk-scan + x_cat + input projection -> g_xw
// Block = 256 threads (8 warps) = one batch. Warp w owns t in [128w, 128w+128).
// Lane owns d-pair (2l, 2l+1). Weights staged via smem (transposed, coalesced).
// ============================================================================
__global__ void __launch_bounds__(256, 2) k1_syn_proj(
    const float* __restrict__ inputs,   // [B,T,64]
    const float* __restrict__ syn_x0,   // [B,64]
    const float* __restrict__ w_ih,     // [128,16]
    float* __restrict__ out_xcat)       // [B,T,128]
{
    __shared__ float wT[HH][2*DD];      // transposed weights [16][128]
    __shared__ float Asm[NW][DD];
    __shared__ float Bsm[NW][DD];
    __shared__ float Ssm[NW][DD];

    const int b    = blockIdx.x;
    const int tid  = threadIdx.x;
    const int w    = tid >> 5;
    const int lane = tid & 31;
    const int t0   = w * CH;

    // ---- stage transposed weights (coalesced-ish LDG, one pass) ----
    for (int idx = tid; idx < 2*DD*HH; idx += 256) {
        int d = idx & 127;
        int h = idx >> 7;
        wT[h][d] = w_ih[d*HH + h];
    }
    __syncthreads();

    // ---- register-stationary weights via conflict-free LDS.64 ----
    u64 wA[HH], wB[HH];
#pragma unroll
    for (int h = 0; h < HH; h++) {
        float2 a = *reinterpret_cast<const float2*>(&wT[h][2*lane]);
        float2 bb = *reinterpret_cast<const float2*>(&wT[h][64 + 2*lane]);
        wA[h] = pk2(a.x, a.y);
        wB[h] = pk2(bb.x, bb.y);
    }

    const float2* ip = reinterpret_cast<const float2*>(inputs)
                       + ((size_t)b*TT + t0)*(DD/2) + lane;

    // ---- phase 1: compose chunk affine (A,B) per owned d ----
    {
        float2 A  = make_float2(1.f, 1.f);
        float2 Bc = make_float2(0.f, 0.f);
        float2 buf[4];
#pragma unroll
        for (int k = 0; k < 4; k++) buf[k] = ip[k*(DD/2)];
        for (int t = 0; t < CH; t++) {
            float2 in = buf[t & 3];
            if (t + 4 < CH) buf[t & 3] = ip[(t + 4)*(DD/2)];
            float kx = fmaf(0.5f, in.x, INV_TAU);
            float ky = fmaf(0.5f, in.y, INV_TAU);
            float ex = expnk(kx);
            float ey = expnk(ky);
            float rx = __fdividef(INV_TAU, kx);
            float ry = __fdividef(INV_TAU, ky);
            float bx = fmaf(-rx, ex, rx);      // r(1-e)
            float by = fmaf(-ry, ey, ry);
            A.x *= ex;  A.y *= ey;
            Bc.x = fmaf(ex, Bc.x, bx);
            Bc.y = fmaf(ey, Bc.y, by);
        }
        *reinterpret_cast<float2*>(&Asm[w][2*lane]) = A;
        *reinterpret_cast<float2*>(&Bsm[w][2*lane]) = Bc;
    }
    __syncthreads();

    // ---- phase 2: exclusive block scan over 8 chunks, per d ----
    if (tid < DD) {
        float s = syn_x0[b*DD + tid];
#pragma unroll
        for (int c = 0; c < NW; c++) {
            Ssm[c][tid] = s;
            s = fmaf(Asm[c][tid], s, Bsm[c][tid]);
        }
    }
    __syncthreads();

    // ---- phase 3: re-stream inputs (L2 hits), emit x_cat + xw ----
    float2 s = *reinterpret_cast<float2*>(&Ssm[w][2*lane]);
    float2* xc = reinterpret_cast<float2*>(out_xcat)
                 + ((size_t)b*TT + t0)*DD + lane;
    float* xwp = g_xw + ((size_t)b*TT + t0)*HH;
    const int hsel = ((lane & 1) << 3) | ((lane & 2) << 1)
                   | ((lane & 4) >> 1) | ((lane & 8) >> 3);

    float2 buf[4];
#pragma unroll
    for (int k = 0; k < 4; k++) buf[k] = ip[k*(DD/2)];

    for (int t = 0; t < CH; t++) {
        float2 in = buf[t & 3];
        if (t + 4 < CH) buf[t & 3] = ip[(t + 4)*(DD/2)];

        float kx = fmaf(0.5f, in.x, INV_TAU);
        float ky = fmaf(0.5f, in.y, INV_TAU);
        float ex = expnk(kx);
        float ey = expnk(ky);
        float rx = __fdividef(INV_TAU, kx);
        float ry = __fdividef(INV_TAU, ky);

        float2 sx;                       // syn(pre-update) * input
        sx.x = s.x * in.x;
        sx.y = s.y * in.y;

        xc[t*DD]      = in;              // x_cat[:, :64]
        xc[t*DD + 32] = sx;              // x_cat[:, 64:]

        s.x = fmaf(ex, s.x - rx, rx);
        s.y = fmaf(ey, s.y - ry, ry);

        // ---- projection partials over this lane's 2 d's ----
        u64 inP = pk2(in.x, in.y);
        u64 sxP = pk2(sx.x, sx.y);
        float p16[16];
#pragma unroll
        for (int h = 0; h < HH; h++) {
            u64 a = mul2(inP, wA[h]);
            a = fma2(sxP, wB[h], a);
            p16[h] = hadd2(a);
        }

        // ---- vector-halving butterfly; lane<16 ends holding xw[bitrev4(lane)]
        float p8[8];
#pragma unroll
        for (int i = 0; i < 8; i++) {
            bool lo = (lane & 1) == 0;
            float send = lo ? p16[8 + i] : p16[i];
            float recv = __shfl_xor_sync(0xffffffffu, send, 1);
            p8[i] = (lo ? p16[i] : p16[8 + i]) + recv;
        }
        float p4[4];
#pragma unroll
        for (int i = 0; i < 4; i++) {
            bool lo = (lane & 2) == 0;
            float send = lo ? p8[4 + i] : p8[i];
            float recv = __shfl_xor_sync(0xffffffffu, send, 2);
            p4[i] = (lo ? p8[i] : p8[4 + i]) + recv;
        }
        float p2[2];
#pragma unroll
        for (int i = 0; i < 2; i++) {
            bool lo = (lane & 4) == 0;
            float send = lo ? p4[2 + i] : p4[i];
            float recv = __shfl_xor_sync(0xffffffffu, send, 4);
            p2[i] = (lo ? p4[i] : p4[2 + i]) + recv;
        }
        float xwv;
        {
            bool lo = (lane & 8) == 0;
            float send = lo ? p2[1] : p2[0];
            float recv = __shfl_xor_sync(0xffffffffu, send, 8);
            xwv = (lo ? p2[0] : p2[1]) + recv;
            xwv += __shfl_xor_sync(0xffffffffu, xwv, 16);
        }

        if (lane < HH) xwp[t*HH + hsel] = xwv;
    }
}

// ============================================================================
// K2: sequential ReLU RNN + hidden + linear output. One warp per batch.
// Half-warp i-split: lanes 0-15 accumulate i=0..7, lanes 16-31 i=8..15.
// ============================================================================
__global__ void __launch_bounds__(32) k2_rnn(
    const float* __restrict__ h0,       // [B,16]
    const float* __restrict__ w_hh,     // [16,16]
    const float* __restrict__ bias,     // [16]
    const float* __restrict__ lin_w,    // [16]
    const float* __restrict__ lin_b,    // [1]
    float* __restrict__ out_output,     // [B,T]
    float* __restrict__ out_hidden)     // [B,T,16]
{
    const int lane  = threadIdx.x;
    const int b     = blockIdx.x;
    const int j     = lane & 15;
    const int ibase = (lane < 16) ? 0 : 8;

    float whh[8];
#pragma unroll
    for (int k = 0; k < 8; k++) whh[k] = w_hh[(ibase + k)*HH + j];
    const float biasj = bias[j];
    const float lwj   = lin_w[j];
    const float lb    = lin_b[0];

    float hj = h0[b*HH + j];            // lane holds h[j]; halves mirrored

    const float* xp = g_xw + (size_t)b*TT*HH + j;
    float*      hid = out_hidden + (size_t)b*TT*HH;
    float*       op = out_output + (size_t)b*TT;

    float buf[4];
#pragma unroll
    for (int p = 0; p < 4; p++) buf[p] = xp[p*HH];

    for (int t = 0; t < TT; t++) {
        float xwv = buf[t & 3];
        if (t + 4 < TT) buf[t & 3] = xp[(t + 4)*HH];

        float a0 = (lane < 16) ? xwv : biasj;
        float a1 = 0.0f;
#pragma unroll
        for (int k = 0; k < 8; k += 2) {
            float hA = __shfl_sync(0xffffffffu, hj, ibase + k);
            float hB = __shfl_sync(0xffffffffu, hj, ibase + k + 1);
            a0 = fmaf(hA, whh[k],     a0);
            a1 = fmaf(hB, whh[k + 1], a1);
        }
        float acc = a0 + a1;
        float tot = acc + __shfl_xor_sync(0xffffffffu, acc, 16);
        hj = fmaxf(tot, 0.0f);

        if (lane < HH) hid[t*HH + j] = hj;

        float v = hj * lwj;
        v += __shfl_xor_sync(0xffffffffu, v, 8);
        v += __shfl_xor_sync(0xffffffffu, v, 4);
        v += __shfl_xor_sync(0xffffffffu, v, 2);
        v += __shfl_xor_sync(0xffffffffu, v, 1);
        if (lane == 0) op[t] = v + lb;
    }
}

extern "C" void kernel_launch(void* const* d_in, const int* in_sizes, int n_in,
                              void* d_out, int out_size) {
    const float* inputs = (const float*)d_in[0];   // [B,T,64]
    const float* syn_x0 = (const float*)d_in[1];   // [B,64]
    const float* h0     = (const float*)d_in[2];   // [B,16]
    const float* w_ih   = (const float*)d_in[3];   // [128,16]
    const float* w_hh   = (const float*)d_in[4];   // [16,16]
    const float* bias   = (const float*)d_in[5];   // [16]
    const float* lin_w  = (const float*)d_in[6];   // [16,1]
    const float* lin_b  = (const float*)d_in[7];   // [1]

    float* out = (float*)d_out;
    // tuple concat order: output [B,T,1], hidden [B,T,16], x_cat [B,T,128]
    float* out_output = out;
    float* out_hidden = out + (size_t)BB*TT;
    float* out_xcat   = out + (size_t)BB*TT + (size_t)BB*TT*HH;

    k1_syn_proj<<<BB, 256>>>(inputs, syn_x0, w_ih, out_xcat);
    k2_rnn<<<BB, 32>>>(h0, w_hh, bias, lin_w, lin_b, out_output, out_hidden);
}

// round 6
// speedup vs baseline: 1.1204x; 1.1099x over previous
#include <cuda_runtime.h>

#define BB 2048
#define TT 1024
#define DD 64
#define HH 16
#define NW 8               // warps per K1 block
#define CH 128             // timesteps per K1 warp
#define INV_TAU (1.0f/6.0f)

typedef unsigned long long u64;

// xw scratch: [B, T, 16]
__device__ float g_xw[(size_t)BB * TT * HH];

__device__ __forceinline__ u64 pk2(float lo, float hi) {
    u64 r; asm("mov.b64 %0, {%1,%2};" : "=l"(r) : "f"(lo), "f"(hi)); return r;
}
__device__ __forceinline__ u64 mul2(u64 a, u64 b) {
    u64 r; asm("mul.rn.f32x2 %0, %1, %2;" : "=l"(r) : "l"(a), "l"(b)); return r;
}
__device__ __forceinline__ u64 fma2(u64 a, u64 b, u64 c) {
    u64 r; asm("fma.rn.f32x2 %0, %1, %2, %3;" : "=l"(r) : "l"(a), "l"(b), "l"(c)); return r;
}
__device__ __forceinline__ u64 add2(u64 a, u64 b) {
    u64 r; asm("add.rn.f32x2 %0, %1, %2;" : "=l"(r) : "l"(a), "l"(b)); return r;
}

// exp(-k) for k in [1/6, 2/3): degree-5 poly about c=5/12. rel err ~4e-7.
// FFMA-imm (rt=1), no const registers.
__device__ __forceinline__ float expnk(float k) {
    const float E = 0.6592406302004438f;         // exp(-5/12)
    float x = k - 0.4166666666666667f;
    float p = -E / 120.0f;
    p = fmaf(p, x,  E / 24.0f);
    p = fmaf(p, x, -E / 6.0f);
    p = fmaf(p, x,  E * 0.5f);
    p = fmaf(p, x, -E);
    p = fmaf(p, x,  E);
    return p;
}

// ============================================================================
// K1: synaptic chunk-scan + x_cat + input projection -> g_xw
// Block = 256 threads (8 warps) = one batch. Warp w owns t in [128w, 128w+128).
// Lane owns d-pair (2l, 2l+1). Projection uses h-packed f32x2 accumulators;
// butterfly reduce on u64 values; lane<16 ends holding xw[bitrev4(lane)].
// ============================================================================
__global__ void __launch_bounds__(256, 2) k1_syn_proj(
    const float* __restrict__ inputs,   // [B,T,64]
    const float* __restrict__ syn_x0,   // [B,64]
    const float* __restrict__ w_ih,     // [128,16]
    float* __restrict__ out_xcat)       // [B,T,128]
{
    __shared__ float wsm[2*DD][HH];     // raw copy of w_ih
    __shared__ float Asm[NW][DD];
    __shared__ float Bsm[NW][DD];
    __shared__ float Ssm[NW][DD];

    const int b    = blockIdx.x;
    const int tid  = threadIdx.x;
    const int w    = tid >> 5;
    const int lane = tid & 31;
    const int t0   = w * CH;

    // ---- stage weights to smem (coalesced float4) ----
    {
        const float4* src = reinterpret_cast<const float4*>(w_ih);
        float4* dst = reinterpret_cast<float4*>(&wsm[0][0]);
        for (int i = tid; i < 2*DD*HH/4; i += 256) dst[i] = src[i];
    }
    __syncthreads();

    // ---- register-stationary weights, h-packed u64 pairs ----
    // wa0[i] = (W[2l][2i], W[2l][2i+1]), wa1: row 2l+1, wb0/wb1: rows 64+2l/65+2l
    u64 wa0[8], wa1[8], wb0[8], wb1[8];
#pragma unroll
    for (int i = 0; i < 8; i++) {
        wa0[i] = *reinterpret_cast<const u64*>(&wsm[2*lane   ][2*i]);
        wa1[i] = *reinterpret_cast<const u64*>(&wsm[2*lane+1 ][2*i]);
        wb0[i] = *reinterpret_cast<const u64*>(&wsm[64+2*lane][2*i]);
        wb1[i] = *reinterpret_cast<const u64*>(&wsm[65+2*lane][2*i]);
    }

    const float2* ip = reinterpret_cast<const float2*>(inputs)
                       + ((size_t)b*TT + t0)*(DD/2) + lane;

    // ---- phase 1: compose chunk affine (A,B) per owned d ----
    {
        float2 A  = make_float2(1.f, 1.f);
        float2 Bc = make_float2(0.f, 0.f);
        float2 buf[4];
#pragma unroll
        for (int k = 0; k < 4; k++) buf[k] = ip[k*(DD/2)];
        for (int t = 0; t < CH; t++) {
            float2 in = buf[t & 3];
            if (t + 4 < CH) buf[t & 3] = ip[(t + 4)*(DD/2)];
            float kx = fmaf(0.5f, in.x, INV_TAU);
            float ky = fmaf(0.5f, in.y, INV_TAU);
            float ex = expnk(kx);
            float ey = expnk(ky);
            float rx = __fdividef(INV_TAU, kx);
            float ry = __fdividef(INV_TAU, ky);
            float bx = fmaf(-rx, ex, rx);      // r(1-e), FNEG folded
            float by = fmaf(-ry, ey, ry);
            A.x *= ex;  A.y *= ey;
            Bc.x = fmaf(ex, Bc.x, bx);
            Bc.y = fmaf(ey, Bc.y, by);
        }
        *reinterpret_cast<float2*>(&Asm[w][2*lane]) = A;
        *reinterpret_cast<float2*>(&Bsm[w][2*lane]) = Bc;
    }
    __syncthreads();

    // ---- phase 2: exclusive block scan over 8 chunks, per d ----
    if (tid < DD) {
        float s = syn_x0[b*DD + tid];
#pragma unroll
        for (int c = 0; c < NW; c++) {
            Ssm[c][tid] = s;
            s = fmaf(Asm[c][tid], s, Bsm[c][tid]);
        }
    }
    __syncthreads();

    // ---- phase 3: re-stream inputs (L2 hits), emit x_cat + xw ----
    float2 s = *reinterpret_cast<float2*>(&Ssm[w][2*lane]);
    float2* xc = reinterpret_cast<float2*>(out_xcat)
                 + ((size_t)b*TT + t0)*DD + lane;
    float* xwp = g_xw + ((size_t)b*TT + t0)*HH;
    const int hsel = ((lane & 1) << 3) | ((lane & 2) << 1)
                   | ((lane & 4) >> 1) | ((lane & 8) >> 3);

    float2 buf[4];
#pragma unroll
    for (int k = 0; k < 4; k++) buf[k] = ip[k*(DD/2)];

    for (int t = 0; t < CH; t++) {
        float2 in = buf[t & 3];
        if (t + 4 < CH) buf[t & 3] = ip[(t + 4)*(DD/2)];

        float kx = fmaf(0.5f, in.x, INV_TAU);
        float ky = fmaf(0.5f, in.y, INV_TAU);
        float ex = expnk(kx);
        float ey = expnk(ky);
        float rx = __fdividef(INV_TAU, kx);
        float ry = __fdividef(INV_TAU, ky);

        float2 sx;                       // syn(pre-update) * input
        sx.x = s.x * in.x;
        sx.y = s.y * in.y;

        xc[t*DD]      = in;              // x_cat[:, :64]
        xc[t*DD + 32] = sx;              // x_cat[:, 64:]

        float bx = fmaf(-rx, ex, rx);
        float by = fmaf(-ry, ey, ry);
        s.x = fmaf(ex, s.x, bx);
        s.y = fmaf(ey, s.y, by);

        // ---- h-packed projection: acc[i] = (xw[2i], xw[2i+1]) partials ----
        u64 dx0 = pk2(in.x, in.x);
        u64 dx1 = pk2(in.y, in.y);
        u64 ds0 = pk2(sx.x, sx.x);
        u64 ds1 = pk2(sx.y, sx.y);
        u64 acc[8];
#pragma unroll
        for (int i = 0; i < 8; i++) {
            u64 a = mul2(dx0, wa0[i]);
            a = fma2(dx1, wa1[i], a);
            a = fma2(ds0, wb0[i], a);
            a = fma2(ds1, wb1[i], a);
            acc[i] = a;
        }

        // ---- butterfly reduce over 32 lanes on u64 values ----
        u64 q4[4];
        {
            bool lo = (lane & 1) == 0;
#pragma unroll
            for (int i = 0; i < 4; i++) {
                u64 send = lo ? acc[4 + i] : acc[i];
                u64 recv = __shfl_xor_sync(0xffffffffu, send, 1);
                q4[i] = add2(lo ? acc[i] : acc[4 + i], recv);
            }
        }
        u64 q2[2];
        {
            bool lo = (lane & 2) == 0;
#pragma unroll
            for (int i = 0; i < 2; i++) {
                u64 send = lo ? q4[2 + i] : q4[i];
                u64 recv = __shfl_xor_sync(0xffffffffu, send, 2);
                q2[i] = add2(lo ? q4[i] : q4[2 + i], recv);
            }
        }
        u64 q1;
        {
            bool lo = (lane & 4) == 0;
            u64 send = lo ? q2[1] : q2[0];
            u64 recv = __shfl_xor_sync(0xffffffffu, send, 4);
            q1 = add2(lo ? q2[0] : q2[1], recv);
        }
        float xwv;
        {
            float a, bb;
            asm("mov.b64 {%0,%1}, %2;" : "=f"(a), "=f"(bb) : "l"(q1));
            bool lo = (lane & 8) == 0;
            float send = lo ? bb : a;
            float recv = __shfl_xor_sync(0xffffffffu, send, 8);
            xwv = (lo ? a : bb) + recv;
            xwv += __shfl_xor_sync(0xffffffffu, xwv, 16);
        }

        if (lane < HH) xwp[t*HH + hsel] = xwv;
    }
}

// ============================================================================
// K2: sequential ReLU RNN + hidden + linear output. One warp per batch.
// Half-warp i-split; prefetch ring depth 8 (covers ~577-cyc DRAM latency).
// ============================================================================
__global__ void __launch_bounds__(32) k2_rnn(
    const float* __restrict__ h0,       // [B,16]
    const float* __restrict__ w_hh,     // [16,16]
    const float* __restrict__ bias,     // [16]
    const float* __restrict__ lin_w,    // [16]
    const float* __restrict__ lin_b,    // [1]
    float* __restrict__ out_output,     // [B,T]
    float* __restrict__ out_hidden)     // [B,T,16]
{
    const int lane  = threadIdx.x;
    const int b     = blockIdx.x;
    const int j     = lane & 15;
    const int ibase = (lane < 16) ? 0 : 8;

    float whh[8];
#pragma unroll
    for (int k = 0; k < 8; k++) whh[k] = w_hh[(ibase + k)*HH + j];
    const float biasj = bias[j];
    const float lwj   = lin_w[j];
    const float lb    = lin_b[0];

    float hj = h0[b*HH + j];            // lane holds h[j]; halves mirrored

    const float* xp = g_xw + (size_t)b*TT*HH + j;
    float*      hid = out_hidden + (size_t)b*TT*HH;
    float*       op = out_output + (size_t)b*TT;

    float buf[8];
#pragma unroll
    for (int p = 0; p < 8; p++) buf[p] = xp[p*HH];

    for (int t = 0; t < TT; t++) {
        float xwv = buf[t & 7];
        if (t + 8 < TT) buf[t & 7] = xp[(t + 8)*HH];

        float a0 = (lane < 16) ? xwv : biasj;
        float a1 = 0.0f;
#pragma unroll
        for (int k = 0; k < 8; k += 2) {
            float hA = __shfl_sync(0xffffffffu, hj, ibase + k);
            float hB = __shfl_sync(0xffffffffu, hj, ibase + k + 1);
            a0 = fmaf(hA, whh[k],     a0);
            a1 = fmaf(hB, whh[k + 1], a1);
        }
        float acc = a0 + a1;
        float tot = acc + __shfl_xor_sync(0xffffffffu, acc, 16);
        hj = fmaxf(tot, 0.0f);

        if (lane < HH) hid[t*HH + j] = hj;

        float v = hj * lwj;
        v += __shfl_xor_sync(0xffffffffu, v, 8);
        v += __shfl_xor_sync(0xffffffffu, v, 4);
        v += __shfl_xor_sync(0xffffffffu, v, 2);
        v += __shfl_xor_sync(0xffffffffu, v, 1);
        if (lane == 0) op[t] = v + lb;
    }
}

extern "C" void kernel_launch(void* const* d_in, const int* in_sizes, int n_in,
                              void* d_out, int out_size) {
    const float* inputs = (const float*)d_in[0];   // [B,T,64]
    const float* syn_x0 = (const float*)d_in[1];   // [B,64]
    const float* h0     = (const float*)d_in[2];   // [B,16]
    const float* w_ih   = (const float*)d_in[3];   // [128,16]
    const float* w_hh   = (const float*)d_in[4];   // [16,16]
    const float* bias   = (const float*)d_in[5];   // [16]
    const float* lin_w  = (const float*)d_in[6];   // [16,1]
    const float* lin_b  = (const float*)d_in[7];   // [1]

    float* out = (float*)d_out;
    // tuple concat order: output [B,T,1], hidden [B,T,16], x_cat [B,T,128]
    float* out_output = out;
    float* out_hidden = out + (size_t)BB*TT;
    float* out_xcat   = out + (size_t)BB*TT + (size_t)BB*TT*HH;

    k1_syn_proj<<<BB, 256>>>(inputs, syn_x0, w_ih, out_xcat);
    k2_rnn<<<BB, 32>>>(h0, w_hh, bias, lin_w, lin_b, out_output, out_hidden);
}